// round 1
// baseline (speedup 1.0000x reference)
#include <cuda_runtime.h>
#include <math.h>

// Problem dims (fixed by setup_inputs)
#define BB 64
#define QQ 1000
#define DD 256
#define NROWS (BB*QQ)          // 64000

#define CONF_LOGIT 0.8472978603872037f   // log(0.7/0.3): sigmoid(x)>0.7
#define NMS_THR 0.5f

// -------- scratch (static device globals: allocation-free rule) --------
__device__ float g_bufA[NROWS * DD];
__device__ float g_bufB[NROWS * DD];
__device__ float g_bufC[NROWS * DD];
__device__ float g_delta[NROWS * 4];
__device__ float g_scores[NROWS];
__device__ unsigned char g_maskL[NROWS];
__device__ unsigned char g_maskR[NROWS];

// =====================================================================
// Kernel 1: candidate mask via per-batch arytenoid list compaction.
// One block per batch. Shared lists of ary boxes (as x1y1x2y2).
// =====================================================================
__global__ void mask_kernel(const float* __restrict__ logits,
                            const float* __restrict__ boxes) {
    __shared__ float4 sL[QQ];
    __shared__ float4 sR[QQ];
    __shared__ int cnt[2];
    const int b = blockIdx.x;
    const int q = threadIdx.x;
    if (q < 2) cnt[q] = 0;
    __syncthreads();

    float l0 = -1e30f, l1 = -1e30f, l4 = -1e30f, l5 = -1e30f;
    float x1 = 0.f, y1 = 0.f, x2 = 0.f, y2 = 0.f;
    if (q < QQ) {
        const float* lg = logits + (size_t)(b * QQ + q) * 6;
        l0 = lg[0]; l1 = lg[1]; l4 = lg[4]; l5 = lg[5];
        const float* bp = boxes + (size_t)(b * QQ + q) * 4;
        float cx = bp[0], cy = bp[1], w = bp[2], h = bp[3];
        x1 = cx - 0.5f * w; y1 = cy - 0.5f * h;
        x2 = cx + 0.5f * w; y2 = cy + 0.5f * h;
        if (l1 > CONF_LOGIT) { int i = atomicAdd(&cnt[0], 1); sL[i] = make_float4(x1, y1, x2, y2); }
        if (l5 > CONF_LOGIT) { int i = atomicAdd(&cnt[1], 1); sR[i] = make_float4(x1, y1, x2, y2); }
    }
    __syncthreads();

    if (q < QQ) {
        const float areai = (x2 - x1) * (y2 - y1);
        bool hl = false, hr = false;
        if (l0 > CONF_LOGIT) {
            const int n = cnt[0];
            for (int j = 0; j < n; j++) {
                float4 o = sL[j];
                float xl = fmaxf(x1, o.x), yt = fmaxf(y1, o.y);
                float xr = fminf(x2, o.z), yb = fminf(y2, o.w);
                float inter = fmaxf(xr - xl, 0.f) * fmaxf(yb - yt, 0.f);
                float uni = areai + (o.z - o.x) * (o.w - o.y) - inter;
                if (inter > NMS_THR * uni) { hl = true; break; }
            }
        }
        if (l4 > CONF_LOGIT) {
            const int n = cnt[1];
            for (int j = 0; j < n; j++) {
                float4 o = sR[j];
                float xl = fmaxf(x1, o.x), yt = fmaxf(y1, o.y);
                float xr = fminf(x2, o.z), yb = fminf(y2, o.w);
                float inter = fmaxf(xr - xl, 0.f) * fmaxf(yb - yt, 0.f);
                float uni = areai + (o.z - o.x) * (o.w - o.y) - inter;
                if (inter > NMS_THR * uni) { hr = true; break; }
            }
        }
        g_maskL[b * QQ + q] = (l0 > CONF_LOGIT) && !hl;
        g_maskR[b * QQ + q] = (l4 > CONF_LOGIT) && !hr;
    }
}

// =====================================================================
// Kernel 2: fp32 SGEMM  C[M,256] = A[M,256] @ W[256,256] + bias (opt relu)
// 128x128 block tile, 16 K-slice, 8x8 per thread, 256 threads.
// M = 64000 (divisible by 128), K = N = 256 (fixed).
// =====================================================================
#define BM 128
#define BN 128
#define BK 16

__global__ __launch_bounds__(256, 2)
void sgemm256(const float* __restrict__ A, const float* __restrict__ W,
              const float* __restrict__ bias, float* __restrict__ C,
              int relu) {
    __shared__ float As[BK][BM];
    __shared__ float Bs[BK][BN];
    const int tid = threadIdx.x;
    const int row0 = blockIdx.y * BM;
    const int col0 = blockIdx.x * BN;
    const int ty = tid >> 4;     // 0..15
    const int tx = tid & 15;     // 0..15

    float acc[8][8];
#pragma unroll
    for (int i = 0; i < 8; i++)
#pragma unroll
        for (int j = 0; j < 8; j++) acc[i][j] = 0.f;

    for (int k0 = 0; k0 < 256; k0 += BK) {
        // Load A tile (128x16) transposed into As[BK][BM]
#pragma unroll
        for (int s = 0; s < 2; s++) {
            int u = tid + s * 256;          // 0..511 float4 units
            int r = u >> 2, c4 = u & 3;
            float4 v = *(const float4*)(A + (size_t)(row0 + r) * 256 + k0 + c4 * 4);
            As[c4 * 4 + 0][r] = v.x;
            As[c4 * 4 + 1][r] = v.y;
            As[c4 * 4 + 2][r] = v.z;
            As[c4 * 4 + 3][r] = v.w;
        }
        // Load B tile (16x128)
#pragma unroll
        for (int s = 0; s < 2; s++) {
            int u = tid + s * 256;
            int r = u >> 5, c4 = u & 31;
            *(float4*)(&Bs[r][c4 * 4]) =
                *(const float4*)(W + (size_t)(k0 + r) * 256 + col0 + c4 * 4);
        }
        __syncthreads();

#pragma unroll
        for (int k = 0; k < BK; k++) {
            float a[8], bf[8];
            *(float4*)(a)     = *(const float4*)(&As[k][ty * 8]);
            *(float4*)(a + 4) = *(const float4*)(&As[k][ty * 8 + 4]);
            *(float4*)(bf)     = *(const float4*)(&Bs[k][tx * 8]);
            *(float4*)(bf + 4) = *(const float4*)(&Bs[k][tx * 8 + 4]);
#pragma unroll
            for (int i = 0; i < 8; i++)
#pragma unroll
                for (int j = 0; j < 8; j++) acc[i][j] += a[i] * bf[j];
        }
        __syncthreads();
    }

    // epilogue: + bias, optional relu
#pragma unroll
    for (int i = 0; i < 8; i++) {
        const int r = row0 + ty * 8 + i;
#pragma unroll
        for (int j = 0; j < 8; j += 4) {
            const int c = col0 + tx * 8 + j;
            float4 v;
            v.x = acc[i][j + 0] + bias[c + 0];
            v.y = acc[i][j + 1] + bias[c + 1];
            v.z = acc[i][j + 2] + bias[c + 2];
            v.w = acc[i][j + 3] + bias[c + 3];
            if (relu) {
                v.x = fmaxf(v.x, 0.f); v.y = fmaxf(v.y, 0.f);
                v.z = fmaxf(v.z, 0.f); v.w = fmaxf(v.w, 0.f);
            }
            *(float4*)(C + (size_t)r * 256 + c) = v;
        }
    }
}

// =====================================================================
// Kernel 3: in-place LayerNorm + ReLU, one warp per row of 256
// =====================================================================
__global__ void ln_relu_kernel(float* __restrict__ X,
                               const float* __restrict__ gma,
                               const float* __restrict__ bta) {
    const int warp = (blockIdx.x * blockDim.x + threadIdx.x) >> 5;
    const int lane = threadIdx.x & 31;
    if (warp >= NROWS) return;
    float* row = X + (size_t)warp * 256;
    float4 v0 = ((float4*)row)[lane * 2];
    float4 v1 = ((float4*)row)[lane * 2 + 1];
    float s = v0.x + v0.y + v0.z + v0.w + v1.x + v1.y + v1.z + v1.w;
    float ss = v0.x * v0.x + v0.y * v0.y + v0.z * v0.z + v0.w * v0.w +
               v1.x * v1.x + v1.y * v1.y + v1.z * v1.z + v1.w * v1.w;
#pragma unroll
    for (int o = 16; o > 0; o >>= 1) {
        s  += __shfl_xor_sync(0xffffffffu, s, o);
        ss += __shfl_xor_sync(0xffffffffu, ss, o);
    }
    const float mu = s * (1.f / 256.f);
    const float var = ss * (1.f / 256.f) - mu * mu;
    const float inv = rsqrtf(var + 1e-5f);
    float4 g0 = ((const float4*)gma)[lane * 2];
    float4 g1 = ((const float4*)gma)[lane * 2 + 1];
    float4 b0 = ((const float4*)bta)[lane * 2];
    float4 b1 = ((const float4*)bta)[lane * 2 + 1];
    float4 o0, o1;
    o0.x = fmaxf((v0.x - mu) * inv * g0.x + b0.x, 0.f);
    o0.y = fmaxf((v0.y - mu) * inv * g0.y + b0.y, 0.f);
    o0.z = fmaxf((v0.z - mu) * inv * g0.z + b0.z, 0.f);
    o0.w = fmaxf((v0.w - mu) * inv * g0.w + b0.w, 0.f);
    o1.x = fmaxf((v1.x - mu) * inv * g1.x + b1.x, 0.f);
    o1.y = fmaxf((v1.y - mu) * inv * g1.y + b1.y, 0.f);
    o1.z = fmaxf((v1.z - mu) * inv * g1.z + b1.z, 0.f);
    o1.w = fmaxf((v1.w - mu) * inv * g1.w + b1.w, 0.f);
    ((float4*)row)[lane * 2]     = o0;
    ((float4*)row)[lane * 2 + 1] = o1;
}

// =====================================================================
// Kernel 4: small heads. delta = m2 @ W_b3 + b_b3 (N=4),
//           scores = ary @ W_s + b_s (N=1). One warp per row.
// =====================================================================
__global__ void head_kernel(const float* __restrict__ m2,
                            const float* __restrict__ ary,
                            const float* __restrict__ W3,
                            const float* __restrict__ b3,
                            const float* __restrict__ Ws,
                            const float* __restrict__ bs) {
    const int row = (blockIdx.x * blockDim.x + threadIdx.x) >> 5;
    const int lane = threadIdx.x & 31;
    if (row >= NROWS) return;
    const float* r2 = m2 + (size_t)row * 256;
    const float* ra = ary + (size_t)row * 256;
    float a0 = 0.f, a1 = 0.f, a2 = 0.f, a3 = 0.f, asc = 0.f;
#pragma unroll
    for (int t = 0; t < 8; t++) {
        const int k = lane + t * 32;
        const float mv = r2[k];
        const float av = ra[k];
        float4 w = ((const float4*)W3)[k];   // W3 row k is exactly a float4
        a0 += mv * w.x; a1 += mv * w.y; a2 += mv * w.z; a3 += mv * w.w;
        asc += av * Ws[k];
    }
#pragma unroll
    for (int o = 16; o > 0; o >>= 1) {
        a0 += __shfl_xor_sync(0xffffffffu, a0, o);
        a1 += __shfl_xor_sync(0xffffffffu, a1, o);
        a2 += __shfl_xor_sync(0xffffffffu, a2, o);
        a3 += __shfl_xor_sync(0xffffffffu, a3, o);
        asc += __shfl_xor_sync(0xffffffffu, asc, o);
    }
    if (lane == 0) {
        g_delta[row * 4 + 0] = a0 + b3[0];
        g_delta[row * 4 + 1] = a1 + b3[1];
        g_delta[row * 4 + 2] = a2 + b3[2];
        g_delta[row * 4 + 3] = a3 + b3[3];
        g_scores[row] = asc + bs[0];
    }
}

// =====================================================================
// Kernel 5: assemble output
// =====================================================================
__device__ __forceinline__ float inv_sigmoid(float x) {
    x = fminf(fmaxf(x, 0.f), 1.f);
    return logf(fmaxf(x, 1e-5f) / fmaxf(1.f - x, 1e-5f));
}
__device__ __forceinline__ float sigmoidf_(float x) {
    return 1.f / (1.f + expf(-x));
}

__global__ void assemble_kernel(const float* __restrict__ boxes,
                                float* __restrict__ out, int write_mask) {
    const int idx = blockIdx.x * blockDim.x + threadIdx.x;
    if (idx >= NROWS) return;
    const float* bp = boxes + (size_t)idx * 4;
    const float cx = bp[0], cy = bp[1], w = bp[2], h = bp[3];
    const float ny = cy + 0.5f * h;
    const float nw = w * 0.8f, nh = h * 0.8f;
    const float d0 = g_delta[idx * 4 + 0];
    const float d1 = g_delta[idx * 4 + 1];
    const float d2 = g_delta[idx * 4 + 2];
    const float d3 = g_delta[idx * 4 + 3];
    const float sc = g_scores[idx];
    const float mL = g_maskL[idx] ? 1.f : 0.f;
    const float mR = g_maskR[idx] ? 1.f : 0.f;
    float* o = out + (size_t)idx * 10;
    // side 0 (left): cand = (cx, ny, nw, nh)
    o[0] = sigmoidf_(d0 + inv_sigmoid(cx)) * mL;
    o[1] = sigmoidf_(d1 + inv_sigmoid(ny)) * mL;
    o[2] = sigmoidf_(d2 + inv_sigmoid(nw)) * mL;
    o[3] = sigmoidf_(d3 + inv_sigmoid(nh)) * mL;
    o[4] = sc * mL;
    // side 1 (right): cand = (cx + 0.1w, ny, nw, nh)
    o[5] = sigmoidf_(d0 + inv_sigmoid(cx + 0.1f * w)) * mR;
    o[6] = sigmoidf_(d1 + inv_sigmoid(ny)) * mR;
    o[7] = sigmoidf_(d2 + inv_sigmoid(nw)) * mR;
    o[8] = sigmoidf_(d3 + inv_sigmoid(nh)) * mR;
    o[9] = sc * mR;
    if (write_mask) {
        out[NROWS * 10 + idx * 2 + 0] = mL;
        out[NROWS * 10 + idx * 2 + 1] = mR;
    }
}

// =====================================================================
extern "C" void kernel_launch(void* const* d_in, const int* in_sizes, int n_in,
                              void* d_out, int out_size) {
    const float* logits   = (const float*)d_in[0];
    const float* boxes    = (const float*)d_in[1];
    const float* features = (const float*)d_in[2];
    // d_in[3] = memory (unused by the reference computation)
    const float* W_p1 = (const float*)d_in[4];
    const float* b_p1 = (const float*)d_in[5];
    const float* ln_g = (const float*)d_in[6];
    const float* ln_b = (const float*)d_in[7];
    const float* W_p2 = (const float*)d_in[8];
    const float* b_p2 = (const float*)d_in[9];
    const float* W_b1 = (const float*)d_in[10];
    const float* b_b1 = (const float*)d_in[11];
    const float* W_b2 = (const float*)d_in[12];
    const float* b_b2 = (const float*)d_in[13];
    const float* W_b3 = (const float*)d_in[14];
    const float* b_b3 = (const float*)d_in[15];
    const float* W_s  = (const float*)d_in[16];
    const float* b_s  = (const float*)d_in[17];
    float* out = (float*)d_out;

    float *bufA, *bufB, *bufC;
    cudaGetSymbolAddress((void**)&bufA, g_bufA);
    cudaGetSymbolAddress((void**)&bufB, g_bufB);
    cudaGetSymbolAddress((void**)&bufC, g_bufC);

    // 1) candidate masks (independent of GEMM chain)
    mask_kernel<<<BB, 1024>>>(logits, boxes);

    const dim3 gGrid(DD / BN, NROWS / BM);  // (2, 500)

    // 2) hdd = relu(LN(features @ W_p1 + b_p1)) -> bufA
    sgemm256<<<gGrid, 256>>>(features, W_p1, b_p1, bufA, 0);
    ln_relu_kernel<<<(NROWS * 32) / 256, 256>>>(bufA, ln_g, ln_b);

    // 3) ary_feat = bufA @ W_p2 + b_p2 -> bufB
    sgemm256<<<gGrid, 256>>>(bufA, W_p2, b_p2, bufB, 0);

    // 4) m1 = relu(bufB @ W_b1 + b_b1) -> bufA
    sgemm256<<<gGrid, 256>>>(bufB, W_b1, b_b1, bufA, 1);

    // 5) m2 = relu(bufA @ W_b2 + b_b2) -> bufC
    sgemm256<<<gGrid, 256>>>(bufA, W_b2, b_b2, bufC, 1);

    // 6) delta = m2 @ W_b3 + b_b3 ; scores = ary_feat @ W_s + b_s
    head_kernel<<<(NROWS * 32) / 256, 256>>>(bufC, bufB, W_b3, b_b3, W_s, b_s);

    // 7) assemble [B,Q,2,5] (+ cand_mask region if present)
    const int write_mask = (out_size >= NROWS * 10 + NROWS * 2) ? 1 : 0;
    assemble_kernel<<<(NROWS + 255) / 256, 256>>>(boxes, out, write_mask);
}

// round 5
// speedup vs baseline: 1.6036x; 1.6036x over previous
#include <cuda_runtime.h>
#include <cuda_bf16.h>
#include <math.h>
#include <stdint.h>

// Problem dims (fixed by setup_inputs)
#define BB 64
#define QQ 1000
#define DD 256
#define NROWS (BB*QQ)          // 64000

#define CONF_LOGIT 0.8472978603872037f   // log(0.7/0.3): sigmoid(x)>0.7
#define NMS_THR 0.5f

// -------- scratch (static device globals: allocation-free rule) --------
__device__ __nv_bfloat16 g_split[NROWS * 512];     // activation split: [row][hi(256)|lo(256)]
__device__ float g_f32a[NROWS * DD];               // GEMM1 out (pre-LN)
__device__ float g_f32b[NROWS * DD];               // ary_feat (score head input)
__device__ float g_f32c[NROWS * DD];               // m2 (delta head input)
__device__ __nv_bfloat16 g_wt[4 * 256 * 512];      // weights, transposed+split: [n][hi(256)|lo(256)]
__device__ float g_delta[NROWS * 4];
__device__ float g_scores[NROWS];
__device__ unsigned char g_maskL[NROWS];
__device__ unsigned char g_maskR[NROWS];

// =====================================================================
// Kernel 1: candidate mask via per-batch arytenoid list compaction.
// =====================================================================
__global__ void mask_kernel(const float* __restrict__ logits,
                            const float* __restrict__ boxes) {
    __shared__ float4 sL[QQ];
    __shared__ float4 sR[QQ];
    __shared__ int cnt[2];
    const int b = blockIdx.x;
    const int q = threadIdx.x;
    if (q < 2) cnt[q] = 0;
    __syncthreads();

    float l0 = -1e30f, l1 = -1e30f, l4 = -1e30f, l5 = -1e30f;
    float x1 = 0.f, y1 = 0.f, x2 = 0.f, y2 = 0.f;
    if (q < QQ) {
        const float* lg = logits + (size_t)(b * QQ + q) * 6;
        l0 = lg[0]; l1 = lg[1]; l4 = lg[4]; l5 = lg[5];
        const float* bp = boxes + (size_t)(b * QQ + q) * 4;
        float cx = bp[0], cy = bp[1], w = bp[2], h = bp[3];
        x1 = cx - 0.5f * w; y1 = cy - 0.5f * h;
        x2 = cx + 0.5f * w; y2 = cy + 0.5f * h;
        if (l1 > CONF_LOGIT) { int i = atomicAdd(&cnt[0], 1); sL[i] = make_float4(x1, y1, x2, y2); }
        if (l5 > CONF_LOGIT) { int i = atomicAdd(&cnt[1], 1); sR[i] = make_float4(x1, y1, x2, y2); }
    }
    __syncthreads();

    if (q < QQ) {
        const float areai = (x2 - x1) * (y2 - y1);
        bool hl = false, hr = false;
        if (l0 > CONF_LOGIT) {
            const int n = cnt[0];
            for (int j = 0; j < n; j++) {
                float4 o = sL[j];
                float xl = fmaxf(x1, o.x), yt = fmaxf(y1, o.y);
                float xr = fminf(x2, o.z), yb = fminf(y2, o.w);
                float inter = fmaxf(xr - xl, 0.f) * fmaxf(yb - yt, 0.f);
                float uni = areai + (o.z - o.x) * (o.w - o.y) - inter;
                if (inter > NMS_THR * uni) { hl = true; break; }
            }
        }
        if (l4 > CONF_LOGIT) {
            const int n = cnt[1];
            for (int j = 0; j < n; j++) {
                float4 o = sR[j];
                float xl = fmaxf(x1, o.x), yt = fmaxf(y1, o.y);
                float xr = fminf(x2, o.z), yb = fminf(y2, o.w);
                float inter = fmaxf(xr - xl, 0.f) * fmaxf(yb - yt, 0.f);
                float uni = areai + (o.z - o.x) * (o.w - o.y) - inter;
                if (inter > NMS_THR * uni) { hr = true; break; }
            }
        }
        g_maskL[b * QQ + q] = (l0 > CONF_LOGIT) && !hl;
        g_maskR[b * QQ + q] = (l4 > CONF_LOGIT) && !hr;
    }
}

// =====================================================================
// Conversion helpers
// =====================================================================
__device__ __forceinline__ void split_bf16(float v, __nv_bfloat16& h, __nv_bfloat16& l) {
    h = __float2bfloat16(v);
    l = __float2bfloat16(v - __bfloat162float(h));
}

// Weights: W[256][256] fp32 -> Wt[n=256][hi k 0..255 | lo k 256..511] bf16
__global__ void wconv_kernel(const float* __restrict__ W0, const float* __restrict__ W1,
                             const float* __restrict__ W2, const float* __restrict__ W3) {
    const int w = blockIdx.y;
    const float* Ws = (w == 0) ? W0 : (w == 1) ? W1 : (w == 2) ? W2 : W3;
    const int idx = blockIdx.x * blockDim.x + threadIdx.x;   // 0..65535
    const int k = idx >> 8;
    const int n = idx & 255;
    float v = Ws[k * 256 + n];
    __nv_bfloat16 h, l;
    split_bf16(v, h, l);
    __nv_bfloat16* Wt = g_wt + (size_t)w * 256 * 512;
    Wt[n * 512 + k] = h;
    Wt[n * 512 + 256 + k] = l;
}

// features fp32 [M][256] -> g_split [M][512]
__global__ void fconv_kernel(const float* __restrict__ F) {
    const int t = blockIdx.x * blockDim.x + threadIdx.x;   // M*32 threads, 8 elems each
    if (t >= NROWS * 32) return;
    const int r = t >> 5;
    const int c = (t & 31) * 8;
    float4 v0 = *(const float4*)(F + (size_t)r * 256 + c);
    float4 v1 = *(const float4*)(F + (size_t)r * 256 + c + 4);
    __nv_bfloat16 h[8], l[8];
    split_bf16(v0.x, h[0], l[0]); split_bf16(v0.y, h[1], l[1]);
    split_bf16(v0.z, h[2], l[2]); split_bf16(v0.w, h[3], l[3]);
    split_bf16(v1.x, h[4], l[4]); split_bf16(v1.y, h[5], l[5]);
    split_bf16(v1.z, h[6], l[6]); split_bf16(v1.w, h[7], l[7]);
    *(uint4*)(g_split + (size_t)r * 512 + c)       = *(uint4*)h;
    *(uint4*)(g_split + (size_t)r * 512 + 256 + c) = *(uint4*)l;
}

// =====================================================================
// bf16 split-K tensor-core GEMM.
// C[M,256] = A[M,256] @ W[256,256] + bias ; emulated fp32 via
//   Ahi*Whi + Alo*Whi + Ahi*Wlo  as one K=768 bf16 MMA chain.
// A source: g_split [M][512] (hi|lo). W source: g_wt slice [256n][512] (hi|lo).
// Block: 128 rows x 256 cols (full N), 512 threads = 16 warps (2x8), warp 64x32.
// =====================================================================
#define KCH 32                      // k chunk (bf16 elems)
#define NCHUNK 24                   // 768 / 32
#define SA 40                       // padded smem row stride (halves)
#define A_STAGE_B (128 * SA * 2)    // 10240 B
#define B_STAGE_B (256 * SA * 2)    // 20480 B
#define STAGE_B (A_STAGE_B + B_STAGE_B)

__device__ __forceinline__ void ldsm_x4(uint32_t& r0, uint32_t& r1, uint32_t& r2, uint32_t& r3,
                                        uint32_t addr) {
    asm volatile("ldmatrix.sync.aligned.m8n8.x4.shared.b16 {%0,%1,%2,%3}, [%4];"
                 : "=r"(r0), "=r"(r1), "=r"(r2), "=r"(r3) : "r"(addr));
}
__device__ __forceinline__ void mma_bf16(float& c0, float& c1, float& c2, float& c3,
                                         uint32_t a0, uint32_t a1, uint32_t a2, uint32_t a3,
                                         uint32_t b0, uint32_t b1) {
    asm volatile("mma.sync.aligned.m16n8k16.row.col.f32.bf16.bf16.f32 "
                 "{%0,%1,%2,%3}, {%4,%5,%6,%7}, {%8,%9}, {%0,%1,%2,%3};"
                 : "+f"(c0), "+f"(c1), "+f"(c2), "+f"(c3)
                 : "r"(a0), "r"(a1), "r"(a2), "r"(a3), "r"(b0), "r"(b1));
}
__device__ __forceinline__ void cp16(uint32_t saddr, const void* gaddr) {
    asm volatile("cp.async.cg.shared.global [%0], [%1], 16;" :: "r"(saddr), "l"(gaddr));
}

__global__ __launch_bounds__(512, 1)
void gemm_bf16split(const __nv_bfloat16* __restrict__ Ain,  // [M][512]
                    const __nv_bfloat16* __restrict__ Wt,   // [256][512]
                    const float* __restrict__ bias,
                    float* __restrict__ outF,               // optional fp32 out
                    __nv_bfloat16* __restrict__ outS,       // optional split out
                    int relu) {
    extern __shared__ char smem[];
    const uint32_t smem_u32 = (uint32_t)__cvta_generic_to_shared(smem);
    const int tid = threadIdx.x;
    const int warp = tid >> 5;
    const int lane = tid & 31;
    const int row0 = blockIdx.x * 128;
    const int wm = (warp >> 3) * 64;    // 0 or 64
    const int wn = (warp & 7) * 32;     // 0..224

    float acc[4][4][4];
#pragma unroll
    for (int i = 0; i < 4; i++)
#pragma unroll
        for (int j = 0; j < 4; j++)
#pragma unroll
            for (int k = 0; k < 4; k++) acc[i][j][k] = 0.f;

    // ---- async copy of one chunk into stage s ----
    auto prefetch = [&](int kk, int s) {
        const int base = kk * KCH;
        const int gA = (base < 512) ? base : base - 512;   // A: hi | lo | hi
        const int gW = (base < 256) ? base : base - 256;   // W: hi | hi | lo
        const uint32_t sA = smem_u32 + s * STAGE_B;
        const uint32_t sB = sA + A_STAGE_B;
        {   // A: 128 rows x 32 halves = 512 x 16B, 1 per thread
            const int r = tid >> 2, c8 = (tid & 3) * 8;
            cp16(sA + (r * SA + c8) * 2, Ain + (size_t)(row0 + r) * 512 + gA + c8);
        }
        {   // B: 256 rows x 32 halves = 1024 x 16B, 2 per thread
#pragma unroll
            for (int s2 = 0; s2 < 2; s2++) {
                const int u = tid + s2 * 512;
                const int n = u >> 2, c8 = (u & 3) * 8;
                cp16(sB + (n * SA + c8) * 2, Wt + (size_t)n * 512 + gW + c8);
            }
        }
        asm volatile("cp.async.commit_group;");
    };

    prefetch(0, 0);
    for (int kk = 0; kk < NCHUNK; kk++) {
        if (kk + 1 < NCHUNK) {
            prefetch(kk + 1, (kk + 1) & 1);
            asm volatile("cp.async.wait_group 1;");
        } else {
            asm volatile("cp.async.wait_group 0;");
        }
        __syncthreads();

        const uint32_t sA = smem_u32 + (kk & 1) * STAGE_B;
        const uint32_t sB = sA + A_STAGE_B;
#pragma unroll
        for (int ks = 0; ks < 2; ks++) {
            const int kb = ks * 16;
            uint32_t a[4][4];
#pragma unroll
            for (int mi = 0; mi < 4; mi++) {
                const int r = wm + mi * 16 + (lane & 15);
                const int c = kb + (lane >> 4) * 8;
                ldsm_x4(a[mi][0], a[mi][1], a[mi][2], a[mi][3], sA + (r * SA + c) * 2);
            }
            uint32_t b[2][4];
#pragma unroll
            for (int nj = 0; nj < 2; nj++) {
                const int nb = wn + nj * 16;
                const int r = nb + (lane & 7) + ((lane >> 4) * 8);
                const int c = kb + (((lane >> 3) & 1) * 8);
                ldsm_x4(b[nj][0], b[nj][1], b[nj][2], b[nj][3], sB + (r * SA + c) * 2);
            }
#pragma unroll
            for (int mi = 0; mi < 4; mi++)
#pragma unroll
                for (int n8 = 0; n8 < 4; n8++) {
                    const uint32_t b0 = b[n8 >> 1][(n8 & 1) * 2];
                    const uint32_t b1 = b[n8 >> 1][(n8 & 1) * 2 + 1];
                    mma_bf16(acc[mi][n8][0], acc[mi][n8][1], acc[mi][n8][2], acc[mi][n8][3],
                             a[mi][0], a[mi][1], a[mi][2], a[mi][3], b0, b1);
                }
        }
        __syncthreads();
    }

    // ---- epilogue ----
#pragma unroll
    for (int mi = 0; mi < 4; mi++) {
        const int r_lo = row0 + wm + mi * 16 + (lane >> 2);
#pragma unroll
        for (int n8 = 0; n8 < 4; n8++) {
            const int col = wn + n8 * 8 + (lane & 3) * 2;
            const float2 bb = *(const float2*)(bias + col);
#pragma unroll
            for (int half = 0; half < 2; half++) {
                const int r = r_lo + half * 8;
                float v0 = acc[mi][n8][half * 2 + 0] + bb.x;
                float v1 = acc[mi][n8][half * 2 + 1] + bb.y;
                if (relu) { v0 = fmaxf(v0, 0.f); v1 = fmaxf(v1, 0.f); }
                if (outF) {
                    float2 o; o.x = v0; o.y = v1;
                    *(float2*)(outF + (size_t)r * 256 + col) = o;
                }
                if (outS) {
                    __nv_bfloat16 h0, l0, h1, l1;
                    split_bf16(v0, h0, l0);
                    split_bf16(v1, h1, l1);
                    __nv_bfloat162 hp; hp.x = h0; hp.y = h1;
                    __nv_bfloat162 lp; lp.x = l0; lp.y = l1;
                    *(__nv_bfloat162*)(outS + (size_t)r * 512 + col) = hp;
                    *(__nv_bfloat162*)(outS + (size_t)r * 512 + 256 + col) = lp;
                }
            }
        }
    }
}

// =====================================================================
// LayerNorm + ReLU: read fp32, write split bf16 into g_split
// =====================================================================
__global__ void ln_relu_split_kernel(const float* __restrict__ X,
                                     const float* __restrict__ gma,
                                     const float* __restrict__ bta) {
    const int warp = (blockIdx.x * blockDim.x + threadIdx.x) >> 5;
    const int lane = threadIdx.x & 31;
    if (warp >= NROWS) return;
    const float* row = X + (size_t)warp * 256;
    float4 v0 = ((const float4*)row)[lane * 2];
    float4 v1 = ((const float4*)row)[lane * 2 + 1];
    float s = v0.x + v0.y + v0.z + v0.w + v1.x + v1.y + v1.z + v1.w;
    float ss = v0.x * v0.x + v0.y * v0.y + v0.z * v0.z + v0.w * v0.w +
               v1.x * v1.x + v1.y * v1.y + v1.z * v1.z + v1.w * v1.w;
#pragma unroll
    for (int o = 16; o > 0; o >>= 1) {
        s  += __shfl_xor_sync(0xffffffffu, s, o);
        ss += __shfl_xor_sync(0xffffffffu, ss, o);
    }
    const float mu = s * (1.f / 256.f);
    const float var = ss * (1.f / 256.f) - mu * mu;
    const float inv = rsqrtf(var + 1e-5f);
    float4 g0 = ((const float4*)gma)[lane * 2];
    float4 g1 = ((const float4*)gma)[lane * 2 + 1];
    float4 b0 = ((const float4*)bta)[lane * 2];
    float4 b1 = ((const float4*)bta)[lane * 2 + 1];
    float r[8];
    r[0] = fmaxf((v0.x - mu) * inv * g0.x + b0.x, 0.f);
    r[1] = fmaxf((v0.y - mu) * inv * g0.y + b0.y, 0.f);
    r[2] = fmaxf((v0.z - mu) * inv * g0.z + b0.z, 0.f);
    r[3] = fmaxf((v0.w - mu) * inv * g0.w + b0.w, 0.f);
    r[4] = fmaxf((v1.x - mu) * inv * g1.x + b1.x, 0.f);
    r[5] = fmaxf((v1.y - mu) * inv * g1.y + b1.y, 0.f);
    r[6] = fmaxf((v1.z - mu) * inv * g1.z + b1.z, 0.f);
    r[7] = fmaxf((v1.w - mu) * inv * g1.w + b1.w, 0.f);
    __nv_bfloat16 h[8], l[8];
#pragma unroll
    for (int i = 0; i < 8; i++) split_bf16(r[i], h[i], l[i]);
    const int c = lane * 8;
    *(uint4*)(g_split + (size_t)warp * 512 + c)       = *(uint4*)h;
    *(uint4*)(g_split + (size_t)warp * 512 + 256 + c) = *(uint4*)l;
}

// =====================================================================
// Heads: delta = m2 @ W_b3 + b_b3 (N=4), scores = ary @ W_s + b_s (N=1)
// =====================================================================
__global__ void head_kernel(const float* __restrict__ m2,
                            const float* __restrict__ ary,
                            const float* __restrict__ W3,
                            const float* __restrict__ b3,
                            const float* __restrict__ Ws,
                            const float* __restrict__ bs) {
    const int row = (blockIdx.x * blockDim.x + threadIdx.x) >> 5;
    const int lane = threadIdx.x & 31;
    if (row >= NROWS) return;
    const float* r2 = m2 + (size_t)row * 256;
    const float* ra = ary + (size_t)row * 256;
    float a0 = 0.f, a1 = 0.f, a2 = 0.f, a3 = 0.f, asc = 0.f;
#pragma unroll
    for (int t = 0; t < 8; t++) {
        const int k = lane + t * 32;
        const float mv = r2[k];
        const float av = ra[k];
        float4 w = ((const float4*)W3)[k];
        a0 += mv * w.x; a1 += mv * w.y; a2 += mv * w.z; a3 += mv * w.w;
        asc += av * Ws[k];
    }
#pragma unroll
    for (int o = 16; o > 0; o >>= 1) {
        a0 += __shfl_xor_sync(0xffffffffu, a0, o);
        a1 += __shfl_xor_sync(0xffffffffu, a1, o);
        a2 += __shfl_xor_sync(0xffffffffu, a2, o);
        a3 += __shfl_xor_sync(0xffffffffu, a3, o);
        asc += __shfl_xor_sync(0xffffffffu, asc, o);
    }
    if (lane == 0) {
        g_delta[row * 4 + 0] = a0 + b3[0];
        g_delta[row * 4 + 1] = a1 + b3[1];
        g_delta[row * 4 + 2] = a2 + b3[2];
        g_delta[row * 4 + 3] = a3 + b3[3];
        g_scores[row] = asc + bs[0];
    }
}

// =====================================================================
// Assemble output
// =====================================================================
__device__ __forceinline__ float inv_sigmoid(float x) {
    x = fminf(fmaxf(x, 0.f), 1.f);
    return logf(fmaxf(x, 1e-5f) / fmaxf(1.f - x, 1e-5f));
}
__device__ __forceinline__ float sigmoidf_(float x) {
    return 1.f / (1.f + expf(-x));
}

__global__ void assemble_kernel(const float* __restrict__ boxes,
                                float* __restrict__ out, int write_mask) {
    const int idx = blockIdx.x * blockDim.x + threadIdx.x;
    if (idx >= NROWS) return;
    const float* bp = boxes + (size_t)idx * 4;
    const float cx = bp[0], cy = bp[1], w = bp[2], h = bp[3];
    const float ny = cy + 0.5f * h;
    const float nw = w * 0.8f, nh = h * 0.8f;
    const float d0 = g_delta[idx * 4 + 0];
    const float d1 = g_delta[idx * 4 + 1];
    const float d2 = g_delta[idx * 4 + 2];
    const float d3 = g_delta[idx * 4 + 3];
    const float sc = g_scores[idx];
    const float mL = g_maskL[idx] ? 1.f : 0.f;
    const float mR = g_maskR[idx] ? 1.f : 0.f;
    float* o = out + (size_t)idx * 10;
    o[0] = sigmoidf_(d0 + inv_sigmoid(cx)) * mL;
    o[1] = sigmoidf_(d1 + inv_sigmoid(ny)) * mL;
    o[2] = sigmoidf_(d2 + inv_sigmoid(nw)) * mL;
    o[3] = sigmoidf_(d3 + inv_sigmoid(nh)) * mL;
    o[4] = sc * mL;
    o[5] = sigmoidf_(d0 + inv_sigmoid(cx + 0.1f * w)) * mR;
    o[6] = sigmoidf_(d1 + inv_sigmoid(ny)) * mR;
    o[7] = sigmoidf_(d2 + inv_sigmoid(nw)) * mR;
    o[8] = sigmoidf_(d3 + inv_sigmoid(nh)) * mR;
    o[9] = sc * mR;
    if (write_mask) {
        out[NROWS * 10 + idx * 2 + 0] = mL;
        out[NROWS * 10 + idx * 2 + 1] = mR;
    }
}

// =====================================================================
extern "C" void kernel_launch(void* const* d_in, const int* in_sizes, int n_in,
                              void* d_out, int out_size) {
    const float* logits   = (const float*)d_in[0];
    const float* boxes    = (const float*)d_in[1];
    const float* features = (const float*)d_in[2];
    // d_in[3] = memory (unused)
    const float* W_p1 = (const float*)d_in[4];
    const float* b_p1 = (const float*)d_in[5];
    const float* ln_g = (const float*)d_in[6];
    const float* ln_b = (const float*)d_in[7];
    const float* W_p2 = (const float*)d_in[8];
    const float* b_p2 = (const float*)d_in[9];
    const float* W_b1 = (const float*)d_in[10];
    const float* b_b1 = (const float*)d_in[11];
    const float* W_b2 = (const float*)d_in[12];
    const float* b_b2 = (const float*)d_in[13];
    const float* W_b3 = (const float*)d_in[14];
    const float* b_b3 = (const float*)d_in[15];
    const float* W_s  = (const float*)d_in[16];
    const float* b_s  = (const float*)d_in[17];
    float* out = (float*)d_out;

    __nv_bfloat16 *S, *Wt;
    float *f32a, *f32b, *f32c;
    cudaGetSymbolAddress((void**)&S, g_split);
    cudaGetSymbolAddress((void**)&Wt, g_wt);
    cudaGetSymbolAddress((void**)&f32a, g_f32a);
    cudaGetSymbolAddress((void**)&f32b, g_f32b);
    cudaGetSymbolAddress((void**)&f32c, g_f32c);

    cudaFuncSetAttribute(gemm_bf16split, cudaFuncAttributeMaxDynamicSharedMemorySize,
                         2 * STAGE_B);

    // 1) candidate masks (independent)
    mask_kernel<<<BB, 1024>>>(logits, boxes);

    // 2) weight split+transpose (tiny) ; feature split
    wconv_kernel<<<dim3(256, 4), 256>>>(W_p1, W_p2, W_b1, W_b2);
    fconv_kernel<<<(NROWS * 32 + 255) / 256, 256>>>(features);

    const int grid = NROWS / 128;   // 500
    const size_t smem = 2 * STAGE_B;

    // 3) GEMM1: features @ W_p1 -> fp32 (pre-LN)
    gemm_bf16split<<<grid, 512, smem>>>(S, Wt + 0 * 256 * 512, b_p1, f32a, nullptr, 0);
    // 4) LN + ReLU -> split
    ln_relu_split_kernel<<<(NROWS * 32) / 256, 256>>>(f32a, ln_g, ln_b);
    // 5) GEMM2: -> ary_feat fp32 (score head) + split (next input), in-place split
    gemm_bf16split<<<grid, 512, smem>>>(S, Wt + 1 * 256 * 512, b_p2, f32b, S, 0);
    // 6) GEMM3: relu -> split only, in-place
    gemm_bf16split<<<grid, 512, smem>>>(S, Wt + 2 * 256 * 512, b_b1, nullptr, S, 1);
    // 7) GEMM4: relu -> fp32 (delta head)
    gemm_bf16split<<<grid, 512, smem>>>(S, Wt + 3 * 256 * 512, b_b2, f32c, nullptr, 1);

    // 8) heads + assemble
    head_kernel<<<(NROWS * 32) / 256, 256>>>(f32c, f32b, W_b3, b_b3, W_s, b_s);
    const int write_mask = (out_size >= NROWS * 10 + NROWS * 2) ? 1 : 0;
    assemble_kernel<<<(NROWS + 255) / 256, 256>>>(boxes, out, write_mask);
}

// round 15
// speedup vs baseline: 1.9622x; 1.2236x over previous
#include <cuda_runtime.h>
#include <cuda_bf16.h>
#include <math.h>
#include <stdint.h>

// Problem dims (fixed by setup_inputs)
#define BB 64
#define QQ 1000
#define DD 256
#define NROWS (BB*QQ)          // 64000

#define CONF_LOGIT 0.8472978603872037f   // log(0.7/0.3): sigmoid(x)>0.7
#define NMS_THR 0.5f

// -------- scratch (static device globals: allocation-free rule) --------
__device__ __nv_bfloat16 g_split[NROWS * 512];     // activation split: [row][hi(256)|lo(256)]
__device__ __nv_bfloat16 g_wt[4 * 256 * 512];      // weights, transposed+split: [n][hi|lo]
__device__ float g_delta[NROWS * 4];
__device__ float g_scores[NROWS];
__device__ unsigned char g_maskL[NROWS];
__device__ unsigned char g_maskR[NROWS];

// =====================================================================
// Kernel 1: candidate mask via per-batch arytenoid list compaction.
// =====================================================================
__global__ void mask_kernel(const float* __restrict__ logits,
                            const float* __restrict__ boxes) {
    __shared__ float4 sL[QQ];
    __shared__ float4 sR[QQ];
    __shared__ int cnt[2];
    const int b = blockIdx.x;
    const int q = threadIdx.x;
    if (q < 2) cnt[q] = 0;
    __syncthreads();

    float l0 = -1e30f, l1 = -1e30f, l4 = -1e30f, l5 = -1e30f;
    float x1 = 0.f, y1 = 0.f, x2 = 0.f, y2 = 0.f;
    if (q < QQ) {
        const float* lg = logits + (size_t)(b * QQ + q) * 6;
        l0 = lg[0]; l1 = lg[1]; l4 = lg[4]; l5 = lg[5];
        const float* bp = boxes + (size_t)(b * QQ + q) * 4;
        float cx = bp[0], cy = bp[1], w = bp[2], h = bp[3];
        x1 = cx - 0.5f * w; y1 = cy - 0.5f * h;
        x2 = cx + 0.5f * w; y2 = cy + 0.5f * h;
        if (l1 > CONF_LOGIT) { int i = atomicAdd(&cnt[0], 1); sL[i] = make_float4(x1, y1, x2, y2); }
        if (l5 > CONF_LOGIT) { int i = atomicAdd(&cnt[1], 1); sR[i] = make_float4(x1, y1, x2, y2); }
    }
    __syncthreads();

    if (q < QQ) {
        const float areai = (x2 - x1) * (y2 - y1);
        bool hl = false, hr = false;
        if (l0 > CONF_LOGIT) {
            const int n = cnt[0];
            for (int j = 0; j < n; j++) {
                float4 o = sL[j];
                float xl = fmaxf(x1, o.x), yt = fmaxf(y1, o.y);
                float xr = fminf(x2, o.z), yb = fminf(y2, o.w);
                float inter = fmaxf(xr - xl, 0.f) * fmaxf(yb - yt, 0.f);
                float uni = areai + (o.z - o.x) * (o.w - o.y) - inter;
                if (inter > NMS_THR * uni) { hl = true; break; }
            }
        }
        if (l4 > CONF_LOGIT) {
            const int n = cnt[1];
            for (int j = 0; j < n; j++) {
                float4 o = sR[j];
                float xl = fmaxf(x1, o.x), yt = fmaxf(y1, o.y);
                float xr = fminf(x2, o.z), yb = fminf(y2, o.w);
                float inter = fmaxf(xr - xl, 0.f) * fmaxf(yb - yt, 0.f);
                float uni = areai + (o.z - o.x) * (o.w - o.y) - inter;
                if (inter > NMS_THR * uni) { hr = true; break; }
            }
        }
        g_maskL[b * QQ + q] = (l0 > CONF_LOGIT) && !hl;
        g_maskR[b * QQ + q] = (l4 > CONF_LOGIT) && !hr;
    }
}

// =====================================================================
// Conversion helpers
// =====================================================================
__device__ __forceinline__ void split_bf16(float v, __nv_bfloat16& h, __nv_bfloat16& l) {
    h = __float2bfloat16(v);
    l = __float2bfloat16(v - __bfloat162float(h));
}

__global__ void wconv_kernel(const float* __restrict__ W0, const float* __restrict__ W1,
                             const float* __restrict__ W2, const float* __restrict__ W3) {
    const int w = blockIdx.y;
    const float* Ws = (w == 0) ? W0 : (w == 1) ? W1 : (w == 2) ? W2 : W3;
    const int idx = blockIdx.x * blockDim.x + threadIdx.x;   // 0..65535
    const int k = idx >> 8;
    const int n = idx & 255;
    float v = Ws[k * 256 + n];
    __nv_bfloat16 h, l;
    split_bf16(v, h, l);
    __nv_bfloat16* Wt = g_wt + (size_t)w * 256 * 512;
    Wt[n * 512 + k] = h;
    Wt[n * 512 + 256 + k] = l;
}

__global__ void fconv_kernel(const float* __restrict__ F) {
    const int t = blockIdx.x * blockDim.x + threadIdx.x;
    if (t >= NROWS * 32) return;
    const int r = t >> 5;
    const int c = (t & 31) * 8;
    float4 v0 = *(const float4*)(F + (size_t)r * 256 + c);
    float4 v1 = *(const float4*)(F + (size_t)r * 256 + c + 4);
    __nv_bfloat16 h[8], l[8];
    split_bf16(v0.x, h[0], l[0]); split_bf16(v0.y, h[1], l[1]);
    split_bf16(v0.z, h[2], l[2]); split_bf16(v0.w, h[3], l[3]);
    split_bf16(v1.x, h[4], l[4]); split_bf16(v1.y, h[5], l[5]);
    split_bf16(v1.z, h[6], l[6]); split_bf16(v1.w, h[7], l[7]);
    *(uint4*)(g_split + (size_t)r * 512 + c)       = *(uint4*)h;
    *(uint4*)(g_split + (size_t)r * 512 + 256 + c) = *(uint4*)l;
}

// =====================================================================
// Fused split-bf16 tensor-core GEMM, 3-stage cp.async pipeline.
// C = A @ W + bias via Ahi*Whi + Alo*Whi + Ahi*Wlo (K=768 bf16).
// Block: 128 rows x 256 cols (FULL N), 512 threads, warp tile 64x32.
// MODE: 0 = split out (+relu)          (GEMM3)
//       1 = LN + relu + split out      (GEMM1)   aux1=ln_g aux2=ln_b
//       2 = split out + score head     (GEMM2)   aux1=W_s  aux2=b_s
//       3 = relu + delta head only     (GEMM4)   aux1=W_b3 aux2=b_b3
// =====================================================================
#define KCH 64                      // k chunk (bf16 elems)
#define NCHUNK 12                   // 768 / 64
#define NSTAGE 3
#define SA 72                       // padded smem row stride (halves)
#define A_STAGE_B (128 * SA * 2)    // 18432 B
#define B_STAGE_B (256 * SA * 2)    // 36864 B
#define STAGE_B (A_STAGE_B + B_STAGE_B)   // 55296 B

__device__ __forceinline__ void ldsm_x4(uint32_t& r0, uint32_t& r1, uint32_t& r2, uint32_t& r3,
                                        uint32_t addr) {
    asm volatile("ldmatrix.sync.aligned.m8n8.x4.shared.b16 {%0,%1,%2,%3}, [%4];"
                 : "=r"(r0), "=r"(r1), "=r"(r2), "=r"(r3) : "r"(addr));
}
__device__ __forceinline__ void mma_bf16(float& c0, float& c1, float& c2, float& c3,
                                         uint32_t a0, uint32_t a1, uint32_t a2, uint32_t a3,
                                         uint32_t b0, uint32_t b1) {
    asm volatile("mma.sync.aligned.m16n8k16.row.col.f32.bf16.bf16.f32 "
                 "{%0,%1,%2,%3}, {%4,%5,%6,%7}, {%8,%9}, {%0,%1,%2,%3};"
                 : "+f"(c0), "+f"(c1), "+f"(c2), "+f"(c3)
                 : "r"(a0), "r"(a1), "r"(a2), "r"(a3), "r"(b0), "r"(b1));
}
__device__ __forceinline__ void cp16(uint32_t saddr, const void* gaddr) {
    asm volatile("cp.async.cg.shared.global [%0], [%1], 16;" :: "r"(saddr), "l"(gaddr));
}

template<int MODE, int RELU>
__global__ __launch_bounds__(512, 1)
void gemm_fused(const __nv_bfloat16* __restrict__ Ain,   // [M][512]
                const __nv_bfloat16* __restrict__ Wt,    // [256][512]
                const float* __restrict__ bias,
                __nv_bfloat16* __restrict__ outS,        // split out (modes 0,1,2)
                const float* __restrict__ aux1,
                const float* __restrict__ aux2) {
    extern __shared__ char smem[];
    const uint32_t smem_u32 = (uint32_t)__cvta_generic_to_shared(smem);
    const int tid = threadIdx.x;
    const int warp = tid >> 5;
    const int lane = tid & 31;
    const int row0 = blockIdx.x * 128;
    const int wm = (warp >> 3) * 64;    // 0 or 64
    const int wn = (warp & 7) * 32;     // 0..224

    float acc[4][4][4];
#pragma unroll
    for (int i = 0; i < 4; i++)
#pragma unroll
        for (int j = 0; j < 4; j++)
#pragma unroll
            for (int k = 0; k < 4; k++) acc[i][j][k] = 0.f;

    auto prefetch = [&](int kk) {
        const int base = kk * KCH;
        const int gA = (base < 512) ? base : base - 512;   // A: hi|lo then hi again
        const int gW = (base < 256) ? base : base - 256;   // W: hi, hi, lo
        const uint32_t sA = smem_u32 + (kk % NSTAGE) * STAGE_B;
        const uint32_t sB = sA + A_STAGE_B;
        {   // A: 128 rows x 64 halves = 1024 x 16B units, 2 per thread
#pragma unroll
            for (int s2 = 0; s2 < 2; s2++) {
                const int u = tid + s2 * 512;
                const int r = u >> 3, c8 = (u & 7) * 8;
                cp16(sA + (r * SA + c8) * 2, Ain + (size_t)(row0 + r) * 512 + gA + c8);
            }
        }
        {   // B: 256 rows x 64 halves = 2048 x 16B units, 4 per thread
#pragma unroll
            for (int s2 = 0; s2 < 4; s2++) {
                const int u = tid + s2 * 512;
                const int n = u >> 3, c8 = (u & 7) * 8;
                cp16(sB + (n * SA + c8) * 2, Wt + (size_t)n * 512 + gW + c8);
            }
        }
        asm volatile("cp.async.commit_group;");
    };

    prefetch(0);
    prefetch(1);
    for (int kk = 0; kk < NCHUNK; kk++) {
        if (kk < NCHUNK - 1) {
            asm volatile("cp.async.wait_group 1;");
        } else {
            asm volatile("cp.async.wait_group 0;");
        }
        __syncthreads();          // chunk kk visible to all; compute(kk-1) done in all warps
        if (kk + 2 < NCHUNK) prefetch(kk + 2);   // overwrites stage (kk-1)%3: safe

        const uint32_t sA = smem_u32 + (kk % NSTAGE) * STAGE_B;
        const uint32_t sB = sA + A_STAGE_B;
#pragma unroll
        for (int ks = 0; ks < 4; ks++) {
            const int kb = ks * 16;
            uint32_t a[4][4];
#pragma unroll
            for (int mi = 0; mi < 4; mi++) {
                const int r = wm + mi * 16 + (lane & 15);
                const int c = kb + (lane >> 4) * 8;
                ldsm_x4(a[mi][0], a[mi][1], a[mi][2], a[mi][3], sA + (r * SA + c) * 2);
            }
            uint32_t b[2][4];
#pragma unroll
            for (int nj = 0; nj < 2; nj++) {
                const int nb = wn + nj * 16;
                const int r = nb + (lane & 7) + ((lane >> 4) * 8);
                const int c = kb + (((lane >> 3) & 1) * 8);
                ldsm_x4(b[nj][0], b[nj][1], b[nj][2], b[nj][3], sB + (r * SA + c) * 2);
            }
#pragma unroll
            for (int mi = 0; mi < 4; mi++)
#pragma unroll
                for (int n8 = 0; n8 < 4; n8++) {
                    const uint32_t b0 = b[n8 >> 1][(n8 & 1) * 2];
                    const uint32_t b1 = b[n8 >> 1][(n8 & 1) * 2 + 1];
                    mma_bf16(acc[mi][n8][0], acc[mi][n8][1], acc[mi][n8][2], acc[mi][n8][3],
                             a[mi][0], a[mi][1], a[mi][2], a[mi][3], b0, b1);
                }
        }
    }
    __syncthreads();   // main-loop smem free for reduction overlay

    // Precompute per-thread column biases
    float2 bb[4];
#pragma unroll
    for (int n8 = 0; n8 < 4; n8++) {
        const int col = wn + n8 * 8 + (lane & 3) * 2;
        bb[n8] = *(const float2*)(bias + col);
    }

    float* red = (float*)smem;

    if (MODE == 1) {
        // ---- LayerNorm + ReLU + split ----
        for (int i = tid; i < 256; i += 512) red[i] = 0.f;
        __syncthreads();
#pragma unroll
        for (int mi = 0; mi < 4; mi++)
#pragma unroll
            for (int half = 0; half < 2; half++) {
                const int r = wm + mi * 16 + (lane >> 2) + half * 8;
                float s = 0.f, ss = 0.f;
#pragma unroll
                for (int n8 = 0; n8 < 4; n8++) {
                    float v0 = acc[mi][n8][half * 2 + 0] + bb[n8].x;
                    float v1 = acc[mi][n8][half * 2 + 1] + bb[n8].y;
                    s += v0 + v1; ss += v0 * v0 + v1 * v1;
                }
                s  += __shfl_xor_sync(0xffffffffu, s, 1);
                s  += __shfl_xor_sync(0xffffffffu, s, 2);
                ss += __shfl_xor_sync(0xffffffffu, ss, 1);
                ss += __shfl_xor_sync(0xffffffffu, ss, 2);
                if ((lane & 3) == 0) {
                    atomicAdd(&red[r], s);
                    atomicAdd(&red[128 + r], ss);
                }
            }
        __syncthreads();
#pragma unroll
        for (int mi = 0; mi < 4; mi++)
#pragma unroll
            for (int half = 0; half < 2; half++) {
                const int r = wm + mi * 16 + (lane >> 2) + half * 8;
                const float mu = red[r] * (1.f / 256.f);
                const float var = red[128 + r] * (1.f / 256.f) - mu * mu;
                const float inv = rsqrtf(var + 1e-5f);
#pragma unroll
                for (int n8 = 0; n8 < 4; n8++) {
                    const int col = wn + n8 * 8 + (lane & 3) * 2;
                    const float2 g2 = *(const float2*)(aux1 + col);
                    const float2 o2 = *(const float2*)(aux2 + col);
                    float v0 = acc[mi][n8][half * 2 + 0] + bb[n8].x;
                    float v1 = acc[mi][n8][half * 2 + 1] + bb[n8].y;
                    v0 = fmaxf((v0 - mu) * inv * g2.x + o2.x, 0.f);
                    v1 = fmaxf((v1 - mu) * inv * g2.y + o2.y, 0.f);
                    __nv_bfloat16 h0, l0, h1, l1;
                    split_bf16(v0, h0, l0); split_bf16(v1, h1, l1);
                    __nv_bfloat162 hp; hp.x = h0; hp.y = h1;
                    __nv_bfloat162 lp; lp.x = l0; lp.y = l1;
                    *(__nv_bfloat162*)(outS + (size_t)(row0 + r) * 512 + col) = hp;
                    *(__nv_bfloat162*)(outS + (size_t)(row0 + r) * 512 + 256 + col) = lp;
                }
            }
    } else if (MODE == 2) {
        // ---- split + score head (no relu) ----
        for (int i = tid; i < 128; i += 512) red[i] = 0.f;
        __syncthreads();
        float ws[4][2];
#pragma unroll
        for (int n8 = 0; n8 < 4; n8++) {
            const int col = wn + n8 * 8 + (lane & 3) * 2;
            ws[n8][0] = aux1[col]; ws[n8][1] = aux1[col + 1];
        }
#pragma unroll
        for (int mi = 0; mi < 4; mi++)
#pragma unroll
            for (int half = 0; half < 2; half++) {
                const int r = wm + mi * 16 + (lane >> 2) + half * 8;
                float s = 0.f;
#pragma unroll
                for (int n8 = 0; n8 < 4; n8++) {
                    const int col = wn + n8 * 8 + (lane & 3) * 2;
                    float v0 = acc[mi][n8][half * 2 + 0] + bb[n8].x;
                    float v1 = acc[mi][n8][half * 2 + 1] + bb[n8].y;
                    s += v0 * ws[n8][0] + v1 * ws[n8][1];
                    __nv_bfloat16 h0, l0, h1, l1;
                    split_bf16(v0, h0, l0); split_bf16(v1, h1, l1);
                    __nv_bfloat162 hp; hp.x = h0; hp.y = h1;
                    __nv_bfloat162 lp; lp.x = l0; lp.y = l1;
                    *(__nv_bfloat162*)(outS + (size_t)(row0 + r) * 512 + col) = hp;
                    *(__nv_bfloat162*)(outS + (size_t)(row0 + r) * 512 + 256 + col) = lp;
                }
                s += __shfl_xor_sync(0xffffffffu, s, 1);
                s += __shfl_xor_sync(0xffffffffu, s, 2);
                if ((lane & 3) == 0) atomicAdd(&red[r], s);
            }
        __syncthreads();
        if (tid < 128) g_scores[row0 + tid] = red[tid] + aux2[0];
    } else if (MODE == 3) {
        // ---- relu + delta head (no tensor output) ----
        red[tid] = 0.f;     // 512 entries
        __syncthreads();
        float w3v[4][2][4];
#pragma unroll
        for (int n8 = 0; n8 < 4; n8++) {
            const int col = wn + n8 * 8 + (lane & 3) * 2;
#pragma unroll
            for (int j = 0; j < 2; j++) {
                const float4 w = ((const float4*)aux1)[col + j];
                w3v[n8][j][0] = w.x; w3v[n8][j][1] = w.y;
                w3v[n8][j][2] = w.z; w3v[n8][j][3] = w.w;
            }
        }
#pragma unroll
        for (int mi = 0; mi < 4; mi++)
#pragma unroll
            for (int half = 0; half < 2; half++) {
                const int r = wm + mi * 16 + (lane >> 2) + half * 8;
                float p0 = 0.f, p1 = 0.f, p2 = 0.f, p3 = 0.f;
#pragma unroll
                for (int n8 = 0; n8 < 4; n8++) {
                    float v0 = fmaxf(acc[mi][n8][half * 2 + 0] + bb[n8].x, 0.f);
                    float v1 = fmaxf(acc[mi][n8][half * 2 + 1] + bb[n8].y, 0.f);
                    p0 += v0 * w3v[n8][0][0] + v1 * w3v[n8][1][0];
                    p1 += v0 * w3v[n8][0][1] + v1 * w3v[n8][1][1];
                    p2 += v0 * w3v[n8][0][2] + v1 * w3v[n8][1][2];
                    p3 += v0 * w3v[n8][0][3] + v1 * w3v[n8][1][3];
                }
#pragma unroll
                for (int o = 1; o <= 2; o <<= 1) {
                    p0 += __shfl_xor_sync(0xffffffffu, p0, o);
                    p1 += __shfl_xor_sync(0xffffffffu, p1, o);
                    p2 += __shfl_xor_sync(0xffffffffu, p2, o);
                    p3 += __shfl_xor_sync(0xffffffffu, p3, o);
                }
                if ((lane & 3) == 0) {
                    atomicAdd(&red[r * 4 + 0], p0);
                    atomicAdd(&red[r * 4 + 1], p1);
                    atomicAdd(&red[r * 4 + 2], p2);
                    atomicAdd(&red[r * 4 + 3], p3);
                }
            }
        __syncthreads();
        {
            const int r = tid >> 2, jj = tid & 3;
            g_delta[(size_t)(row0 + r) * 4 + jj] = red[tid] + aux2[jj];
        }
    } else {
        // ---- MODE 0: plain split out (+relu) ----
#pragma unroll
        for (int mi = 0; mi < 4; mi++)
#pragma unroll
            for (int half = 0; half < 2; half++) {
                const int r = wm + mi * 16 + (lane >> 2) + half * 8;
#pragma unroll
                for (int n8 = 0; n8 < 4; n8++) {
                    const int col = wn + n8 * 8 + (lane & 3) * 2;
                    float v0 = acc[mi][n8][half * 2 + 0] + bb[n8].x;
                    float v1 = acc[mi][n8][half * 2 + 1] + bb[n8].y;
                    if (RELU) { v0 = fmaxf(v0, 0.f); v1 = fmaxf(v1, 0.f); }
                    __nv_bfloat16 h0, l0, h1, l1;
                    split_bf16(v0, h0, l0); split_bf16(v1, h1, l1);
                    __nv_bfloat162 hp; hp.x = h0; hp.y = h1;
                    __nv_bfloat162 lp; lp.x = l0; lp.y = l1;
                    *(__nv_bfloat162*)(outS + (size_t)(row0 + r) * 512 + col) = hp;
                    *(__nv_bfloat162*)(outS + (size_t)(row0 + r) * 512 + 256 + col) = lp;
                }
            }
    }
}

// =====================================================================
// Assemble output
// =====================================================================
__device__ __forceinline__ float inv_sigmoid(float x) {
    x = fminf(fmaxf(x, 0.f), 1.f);
    return logf(fmaxf(x, 1e-5f) / fmaxf(1.f - x, 1e-5f));
}
__device__ __forceinline__ float sigmoidf_(float x) {
    return 1.f / (1.f + expf(-x));
}

__global__ void assemble_kernel(const float* __restrict__ boxes,
                                float* __restrict__ out, int write_mask) {
    const int idx = blockIdx.x * blockDim.x + threadIdx.x;
    if (idx >= NROWS) return;
    const float* bp = boxes + (size_t)idx * 4;
    const float cx = bp[0], cy = bp[1], w = bp[2], h = bp[3];
    const float ny = cy + 0.5f * h;
    const float nw = w * 0.8f, nh = h * 0.8f;
    const float d0 = g_delta[idx * 4 + 0];
    const float d1 = g_delta[idx * 4 + 1];
    const float d2 = g_delta[idx * 4 + 2];
    const float d3 = g_delta[idx * 4 + 3];
    const float sc = g_scores[idx];
    const float mL = g_maskL[idx] ? 1.f : 0.f;
    const float mR = g_maskR[idx] ? 1.f : 0.f;
    float* o = out + (size_t)idx * 10;
    o[0] = sigmoidf_(d0 + inv_sigmoid(cx)) * mL;
    o[1] = sigmoidf_(d1 + inv_sigmoid(ny)) * mL;
    o[2] = sigmoidf_(d2 + inv_sigmoid(nw)) * mL;
    o[3] = sigmoidf_(d3 + inv_sigmoid(nh)) * mL;
    o[4] = sc * mL;
    o[5] = sigmoidf_(d0 + inv_sigmoid(cx + 0.1f * w)) * mR;
    o[6] = sigmoidf_(d1 + inv_sigmoid(ny)) * mR;
    o[7] = sigmoidf_(d2 + inv_sigmoid(nw)) * mR;
    o[8] = sigmoidf_(d3 + inv_sigmoid(nh)) * mR;
    o[9] = sc * mR;
    if (write_mask) {
        out[NROWS * 10 + idx * 2 + 0] = mL;
        out[NROWS * 10 + idx * 2 + 1] = mR;
    }
}

// =====================================================================
extern "C" void kernel_launch(void* const* d_in, const int* in_sizes, int n_in,
                              void* d_out, int out_size) {
    const float* logits   = (const float*)d_in[0];
    const float* boxes    = (const float*)d_in[1];
    const float* features = (const float*)d_in[2];
    // d_in[3] = memory (unused)
    const float* W_p1 = (const float*)d_in[4];
    const float* b_p1 = (const float*)d_in[5];
    const float* ln_g = (const float*)d_in[6];
    const float* ln_b = (const float*)d_in[7];
    const float* W_p2 = (const float*)d_in[8];
    const float* b_p2 = (const float*)d_in[9];
    const float* W_b1 = (const float*)d_in[10];
    const float* b_b1 = (const float*)d_in[11];
    const float* W_b2 = (const float*)d_in[12];
    const float* b_b2 = (const float*)d_in[13];
    const float* W_b3 = (const float*)d_in[14];
    const float* b_b3 = (const float*)d_in[15];
    const float* W_s  = (const float*)d_in[16];
    const float* b_s  = (const float*)d_in[17];
    float* out = (float*)d_out;

    __nv_bfloat16 *S, *Wt;
    cudaGetSymbolAddress((void**)&S, g_split);
    cudaGetSymbolAddress((void**)&Wt, g_wt);

    const size_t smem = NSTAGE * STAGE_B;   // 165888 B
    cudaFuncSetAttribute(gemm_fused<1,1>, cudaFuncAttributeMaxDynamicSharedMemorySize, smem);
    cudaFuncSetAttribute(gemm_fused<2,0>, cudaFuncAttributeMaxDynamicSharedMemorySize, smem);
    cudaFuncSetAttribute(gemm_fused<0,1>, cudaFuncAttributeMaxDynamicSharedMemorySize, smem);
    cudaFuncSetAttribute(gemm_fused<3,1>, cudaFuncAttributeMaxDynamicSharedMemorySize, smem);

    // 1) candidate masks (independent)
    mask_kernel<<<BB, 1024>>>(logits, boxes);

    // 2) weight split+transpose ; feature split
    wconv_kernel<<<dim3(256, 4), 256>>>(W_p1, W_p2, W_b1, W_b2);
    fconv_kernel<<<(NROWS * 32 + 255) / 256, 256>>>(features);

    const int grid = NROWS / 128;   // 500

    // 3) GEMM1 + LN + ReLU -> split (in-place)
    gemm_fused<1,1><<<grid, 512, smem>>>(S, Wt + 0 * 256 * 512, b_p1, S, ln_g, ln_b);
    // 4) GEMM2 -> split (in-place) + scores
    gemm_fused<2,0><<<grid, 512, smem>>>(S, Wt + 1 * 256 * 512, b_p2, S, W_s, b_s);
    // 5) GEMM3 + ReLU -> split (in-place)
    gemm_fused<0,1><<<grid, 512, smem>>>(S, Wt + 2 * 256 * 512, b_b1, S, nullptr, nullptr);
    // 6) GEMM4 + ReLU + delta head (no tensor output)
    gemm_fused<3,1><<<grid, 512, smem>>>(S, Wt + 3 * 256 * 512, b_b2, nullptr, W_b3, b_b3);

    // 7) assemble [B,Q,2,5]
    const int write_mask = (out_size >= NROWS * 10 + NROWS * 2) ? 1 : 0;
    assemble_kernel<<<(NROWS + 255) / 256, 256>>>(boxes, out, write_mask);
}